// round 5
// baseline (speedup 1.0000x reference)
#include <cuda_runtime.h>
#include <cuda_fp16.h>
#include <cstdint>

#define B_   2
#define N_   2048
#define DIM_ 768
#define H_   12
#define DH_  64
#define M1   (B_*N_)     // 4096
#define NC1  (3*DIM_)    // 2304
#define KH2  768         // half2 limb-pairs per GEMM row
#define PITCHB 3072      // bytes per GEMM limb row

// ---------------- device globals ----------------
__device__ uint32_t g_xl[(long)M1*KH2];      // x limbs (h,l)
__device__ uint32_t g_w1[(long)NC1*KH2];     // wqkv limbs (h,l)
__device__ uint32_t g_w2[(long)NC1*KH2];     // wqkv limbs (l,h)
__device__ uint32_t g_p1[(long)DIM_*KH2];    // wp limbs
__device__ uint32_t g_p2[(long)DIM_*KH2];
__device__ uint32_t g_zl[(long)M1*KH2];      // z limbs (attention output)
__device__ uint32_t g_ql[(long)B_*H_*N_*DH_];        // q limbs [bh][n][64]
__device__ uint32_t g_k12[(long)B_*H_*N_*2*DH_];     // k limbs [bh][m][128]: (kh,kl)x64 | (kl,kh)x64
__device__ uint32_t g_vt[(long)B_*H_*DH_*N_];        // v^T limbs [bh][e][m] (vh,vl)
__device__ uint32_t g_vt2[(long)B_*H_*DH_*N_];       // swapped (vl,vh)
__device__ float    g_bq[NC1];
__device__ float    g_bp2[DIM_];

// ---------------- quantizers ----------------
__device__ __forceinline__ float qround8(float x) {        // round-half-even to 2^-8
    float t = __fmaf_rn(x, 256.f, 12582912.f);
    return (t - 12582912.f) * 0.00390625f;
}
__device__ __forceinline__ float q16_8c(float x) {         // with clamp (z saturates)
    float t = __fmaf_rn(x, 256.f, 12582912.f);
    float y = t - 12582912.f;
    y = fminf(fmaxf(y, -32768.f), 32767.f);
    return y * 0.00390625f;
}
__device__ __forceinline__ float q32_16(float x) {
    float t = __fmaf_rn(x, 65536.f, 12582912.f);
    return (t - 12582912.f) * 1.52587890625e-5f;
}
__device__ __forceinline__ uint32_t packu32(__half a, __half b) {
    __half2 t = __halves2half2(a, b);
    return *(uint32_t*)&t;
}

// ---------------- PTX helpers ----------------
__device__ __forceinline__ uint32_t smem_u32(const void* p) {
    uint32_t a;
    asm("{ .reg .u64 t; cvta.to.shared.u64 t, %1; cvt.u32.u64 %0, t; }" : "=r"(a) : "l"(p));
    return a;
}
#define CP_ASYNC16(dst, src) \
    asm volatile("cp.async.cg.shared.global [%0], [%1], 16;" :: "r"(dst), "l"(src) : "memory")
#define CP_COMMIT() asm volatile("cp.async.commit_group;" ::: "memory")
#define CP_WAIT(n)  asm volatile("cp.async.wait_group %0;" :: "n"(n) : "memory")

__device__ __forceinline__ void ldm_x4(uint32_t* r, uint32_t addr) {
    asm volatile("ldmatrix.sync.aligned.m8n8.x4.shared.b16 {%0,%1,%2,%3}, [%4];"
        : "=r"(r[0]), "=r"(r[1]), "=r"(r[2]), "=r"(r[3]) : "r"(addr));
}
__device__ __forceinline__ void mma16816(float* d, const uint32_t* a, const uint32_t* b) {
    asm volatile("mma.sync.aligned.m16n8k16.row.col.f32.f16.f16.f32 "
        "{%0,%1,%2,%3}, {%4,%5,%6,%7}, {%8,%9}, {%0,%1,%2,%3};"
        : "+f"(d[0]), "+f"(d[1]), "+f"(d[2]), "+f"(d[3])
        : "r"(a[0]), "r"(a[1]), "r"(a[2]), "r"(a[3]), "r"(b[0]), "r"(b[1]));
}

// swizzle: XOR 16B-chunk id with row%8 within a 128B group
#define SWP(pitch, row, colb) ((uint32_t)((row)*(pitch) + (((colb)) ^ (((row)&7)<<4))))
#define SWZ(row, colb) SWP(128, row, colb)

// ---------------- kernel 1: quantize + limb-split inputs ----------------
__global__ void prep_kernel(const float* __restrict__ x, const float* __restrict__ wqkv,
                            const float* __restrict__ bqkv, const float* __restrict__ wp,
                            const float* __restrict__ bp) {
    long i = (long)blockIdx.x * blockDim.x + threadIdx.x;
    const long NX = (long)M1 * DIM_;
    const long NW = (long)NC1 * DIM_;
    const long NP = (long)DIM_ * DIM_;
    if (i < NX) {
        float v = q32_16(x[i]);
        __half h = __float2half_rn(v);
        __half l = __float2half_rn(v - __half2float(h));
        g_xl[i] = packu32(h, l);
        return;
    }
    i -= NX;
    if (i < NW) {
        float w = qround8(wqkv[i]);
        __half h = __float2half_rn(w);
        __half l = __float2half_rn(w - __half2float(h));
        g_w1[i] = packu32(h, l);
        g_w2[i] = packu32(l, h);
        return;
    }
    i -= NW;
    if (i < NP) {
        float w = qround8(wp[i]);
        __half h = __float2half_rn(w);
        __half l = __float2half_rn(w - __half2float(h));
        g_p1[i] = packu32(h, l);
        g_p2[i] = packu32(l, h);
        return;
    }
    i -= NP;
    if (i < NC1) { g_bq[i] = qround8(bqkv[i]); return; }
    i -= NC1;
    if (i < DIM_) g_bp2[i] = qround8(bp[i]);
}

// ---------------- GEMM v2: dual-B single pass, 3-stage, 1 sync/chunk ----------------
// Stage: A 16KB | B1 16KB | B2 16KB = 48KB. 24 chunks of 128B (64 halves).
#define GSTG 49152
struct AccTile { float a[2][8][4]; };

__device__ __forceinline__ void gemm_issue2(uint32_t st, const char* Ab, const char* B1b,
                                            const char* B2b, int kbyte, int tid) {
    #pragma unroll
    for (int i = 0; i < 4; i++) {
        int idx = tid + i * 256;
        int row = idx >> 3, c16 = (idx & 7) << 4;
        CP_ASYNC16(st + SWZ(row, c16), Ab + (long)row * PITCHB + kbyte + c16);
    }
    #pragma unroll
    for (int i = 0; i < 4; i++) {
        int idx = tid + i * 256;
        int row = idx >> 3, c16 = (idx & 7) << 4;
        CP_ASYNC16(st + 16384 + SWZ(row, c16), B1b + (long)row * PITCHB + kbyte + c16);
    }
    #pragma unroll
    for (int i = 0; i < 4; i++) {
        int idx = tid + i * 256;
        int row = idx >> 3, c16 = (idx & 7) << 4;
        CP_ASYNC16(st + 32768 + SWZ(row, c16), B2b + (long)row * PITCHB + kbyte + c16);
    }
    CP_COMMIT();
}

__device__ __forceinline__ void gemm_compute2(uint32_t st, AccTile& acc, int wm, int wn, int lane) {
    const int arow_l = (lane & 7) + ((lane >> 3) & 1) * 8;
    const int achk   = (lane >> 4) * 16;
    const int brow_l = (lane & 7) + (lane >> 4) * 8;
    const int bchk   = ((lane >> 3) & 1) * 16;
    #pragma unroll
    for (int kk = 0; kk < 4; kk++) {
        uint32_t a[2][4];
        #pragma unroll
        for (int f = 0; f < 2; f++)
            ldm_x4(a[f], st + SWZ(wm * 32 + f * 16 + arow_l, kk * 32 + achk));
        #pragma unroll
        for (int half = 0; half < 2; half++) {
            uint32_t base = st + 16384 + half * 16384;
            #pragma unroll
            for (int g = 0; g < 4; g++) {
                uint32_t b4[4];
                ldm_x4(b4, base + SWZ(wn * 64 + g * 16 + brow_l, kk * 32 + bchk));
                #pragma unroll
                for (int f = 0; f < 2; f++) {
                    mma16816(acc.a[f][g * 2 + 0], a[f], b4 + 0);
                    mma16816(acc.a[f][g * 2 + 1], a[f], b4 + 2);
                }
            }
        }
    }
}

__device__ __forceinline__ void gemm_main2(const char* Ab, const char* B1b, const char* B2b,
                                           AccTile& acc, char* smem, int tid) {
    uint32_t sb = smem_u32(smem);
    const int lane = tid & 31, wid = tid >> 5;
    const int wm = wid & 3, wn = wid >> 2;
    #pragma unroll
    for (int f = 0; f < 2; f++)
        #pragma unroll
        for (int j = 0; j < 8; j++)
            #pragma unroll
            for (int e = 0; e < 4; e++) acc.a[f][j][e] = 0.f;

    gemm_issue2(sb + 0 * GSTG, Ab, B1b, B2b, 0, tid);
    gemm_issue2(sb + 1 * GSTG, Ab, B1b, B2b, 128, tid);
    #pragma unroll 1
    for (int g = 0; g < 24; g++) {
        if (g + 2 < 24) { CP_WAIT(1); } else { CP_WAIT(0); }
        __syncthreads();
        if (g + 2 < 24)
            gemm_issue2(sb + ((g + 2) % 3) * GSTG, Ab, B1b, B2b, (g + 2) * 128, tid);
        gemm_compute2(sb + (g % 3) * GSTG, acc, wm, wn, lane);
    }
}

// ---------------- kernel 2: QKV projection (HMMA) + attention-layout epilogue ----------------
__global__ void __launch_bounds__(256, 1) gemm_qkv_tc() {
    extern __shared__ char smem[];
    const int tid = threadIdx.x;
    const int m0 = blockIdx.y * 128;
    const int n0 = blockIdx.x * 128;
    AccTile acc;
    gemm_main2((const char*)g_xl + (long)m0 * PITCHB,
               (const char*)g_w1 + (long)n0 * PITCHB,
               (const char*)g_w2 + (long)n0 * PITCHB, acc, smem, tid);

    const int wid = tid >> 5, lane = tid & 31;
    const int wm = wid & 3, wn = wid >> 2;
    const int rb = m0 + wm * 32 + (lane >> 2);
    const int cb = n0 + wn * 64 + (lane & 3) * 2;
    #pragma unroll
    for (int f = 0; f < 2; f++) {
        #pragma unroll
        for (int j = 0; j < 8; j++) {
            #pragma unroll
            for (int cs = 0; cs < 2; cs++) {
                int n = cb + j * 8 + cs;
                float bias = g_bq[n];
                int h = n / 192;
                int rr = n - h * 192;
                int seg = rr >> 6, e = rr & 63;
                #pragma unroll
                for (int rs = 0; rs < 2; rs++) {
                    int m = rb + f * 16 + rs * 8;
                    int bi = m >> 11, nr = m & 2047;
                    long bh = bi * H_ + h;
                    float v = qround8(acc.a[f][j][rs * 2 + cs] + bias);
                    __half hh = __float2half_rn(v);
                    __half ll = __float2half_rn(v - __half2float(hh));
                    if (seg == 0) {
                        g_ql[(bh * N_ + nr) * DH_ + e] = packu32(hh, ll);
                    } else if (seg == 1) {
                        long base = (bh * N_ + nr) * (2 * DH_);
                        g_k12[base + e]       = packu32(hh, ll);
                        g_k12[base + DH_ + e] = packu32(ll, hh);
                    } else {
                        long base = (bh * DH_ + e) * N_ + nr;
                        g_vt[base]  = packu32(hh, ll);
                        g_vt2[base] = packu32(ll, hh);
                    }
                }
            }
        }
    }
}

// ---------------- kernel 4: output projection (HMMA) ----------------
__global__ void __launch_bounds__(256, 1) gemm_proj_tc(float* __restrict__ out) {
    extern __shared__ char smem[];
    const int tid = threadIdx.x;
    const int m0 = blockIdx.y * 128;
    const int n0 = blockIdx.x * 128;
    AccTile acc;
    gemm_main2((const char*)g_zl + (long)m0 * PITCHB,
               (const char*)g_p1 + (long)n0 * PITCHB,
               (const char*)g_p2 + (long)n0 * PITCHB, acc, smem, tid);

    const int wid = tid >> 5, lane = tid & 31;
    const int wm = wid & 3, wn = wid >> 2;
    const int rb = m0 + wm * 32 + (lane >> 2);
    const int cb = n0 + wn * 64 + (lane & 3) * 2;
    #pragma unroll
    for (int f = 0; f < 2; f++) {
        #pragma unroll
        for (int j = 0; j < 8; j++) {
            #pragma unroll
            for (int cs = 0; cs < 2; cs++) {
                int n = cb + j * 8 + cs;
                float bias = g_bp2[n];
                #pragma unroll
                for (int rs = 0; rs < 2; rs++) {
                    int m = rb + f * 16 + rs * 8;
                    out[(long)m * DIM_ + n] = qround8(acc.a[f][j][rs * 2 + cs] + bias);
                }
            }
        }
    }
}

// ---------------- kernel 3: HMMA limb flash-attention ----------------
// smem: Q [128x256B] | K 2 stages [64x512B] | Vt 2 stages [2 bufs x 64x256B] | S [128x256B]
#define AOQ  0u
#define AOK  32768u
#define AOV  98304u
#define AOS  163840u
#define ATTN_SMEM 196608

__device__ __forceinline__ void attn_issue_kv(uint32_t sK_st, uint32_t sV_st,
        const char* kbase, const char* v0base, const char* v1base, int kb, int tid) {
    #pragma unroll
    for (int i = 0; i < 8; i++) {
        int idx = tid + i * 256;
        int row = idx >> 5, c16 = (idx & 31) << 4;
        CP_ASYNC16(sK_st + SWP(512, row, c16), kbase + (long)(kb + row) * 512 + c16);
    }
    #pragma unroll
    for (int i = 0; i < 8; i++) {
        int idx = tid + i * 256;
        int buf = idx >> 10;
        int row = (idx >> 4) & 63;
        int c16 = (idx & 15) << 4;
        const char* vb = buf ? v1base : v0base;
        CP_ASYNC16(sV_st + buf * 16384 + SWP(256, row, c16),
                   vb + (long)row * (N_ * 4) + kb * 4 + c16);
    }
    CP_COMMIT();
}

__global__ void __launch_bounds__(256, 1) attn_tc_kernel() {
    extern __shared__ char smem[];
    const uint32_t sb = smem_u32(smem);
    const int tid = threadIdx.x;
    const int lane = tid & 31, wid = tid >> 5;
    const int wm = wid & 3, wn = wid >> 2;
    const int bh = blockIdx.y;
    const int q0 = blockIdx.x * 128;

    const char* qbase  = (const char*)(g_ql  + (long)bh * N_ * DH_) + (long)q0 * 256;
    const char* kbase  = (const char*)(g_k12 + (long)bh * N_ * 2 * DH_);
    const char* v0base = (const char*)(g_vt  + (long)bh * DH_ * N_);
    const char* v1base = (const char*)(g_vt2 + (long)bh * DH_ * N_);

    // prologue: load Q tile + first K/Vt stage (one group)
    #pragma unroll
    for (int i = 0; i < 8; i++) {
        int idx = tid + i * 256;
        int row = idx >> 4, c16 = (idx & 15) << 4;
        CP_ASYNC16(sb + AOQ + SWP(256, row, c16), qbase + (long)row * 256 + c16);
    }
    attn_issue_kv(sb + AOK, sb + AOV, kbase, v0base, v1base, 0, tid);

    const int arow_l = (lane & 7) + ((lane >> 3) & 1) * 8;
    const int achk   = (lane >> 4) * 16;
    const int brow_l = (lane & 7) + (lane >> 4) * 8;
    const int bchk   = ((lane >> 3) & 1) * 16;
    const int qr     = lane >> 2;       // c-frag row within 8
    const int qc     = (lane & 3) * 2;  // c-frag col pair

    float zacc[2][4][4];
    #pragma unroll
    for (int f = 0; f < 2; f++)
        #pragma unroll
        for (int j = 0; j < 4; j++)
            #pragma unroll
            for (int e = 0; e < 4; e++) zacc[f][j][e] = 0.f;

    #pragma unroll 1
    for (int it = 0; it < 32; it++) {
        const uint32_t sK = sb + AOK + (uint32_t)(it & 1) * 32768u;
        const uint32_t sV = sb + AOV + (uint32_t)(it & 1) * 32768u;
        CP_WAIT(0);
        __syncthreads();
        if (it + 1 < 32)
            attn_issue_kv(sb + AOK + (uint32_t)((it + 1) & 1) * 32768u,
                          sb + AOV + (uint32_t)((it + 1) & 1) * 32768u,
                          kbase, v0base, v1base, (it + 1) * 64, tid);

        // ---- phase 1: s[128x64] = q x k^T (K = 256 limb-halves) ----
        float sacc[2][4][4];
        #pragma unroll
        for (int f = 0; f < 2; f++)
            #pragma unroll
            for (int j = 0; j < 4; j++)
                #pragma unroll
                for (int e = 0; e < 4; e++) sacc[f][j][e] = 0.f;
        #pragma unroll
        for (int kk = 0; kk < 16; kk++) {
            int aoff = (kk & 7) * 32;
            uint32_t a[2][4];
            #pragma unroll
            for (int f = 0; f < 2; f++)
                ldm_x4(a[f], sb + AOQ + SWP(256, wm * 32 + f * 16 + arow_l, aoff + achk));
            #pragma unroll
            for (int g = 0; g < 2; g++) {
                uint32_t b4[4];
                ldm_x4(b4, sK + SWP(512, wn * 32 + g * 16 + brow_l, kk * 32 + bchk));
                #pragma unroll
                for (int f = 0; f < 2; f++) {
                    mma16816(sacc[f][g * 2 + 0], a[f], b4 + 0);
                    mma16816(sacc[f][g * 2 + 1], a[f], b4 + 2);
                }
            }
        }
        // quantize s, split limbs, store interleaved (sh,sl) into sS
        #pragma unroll
        for (int f = 0; f < 2; f++) {
            #pragma unroll
            for (int jn = 0; jn < 4; jn++) {
                #pragma unroll
                for (int rs = 0; rs < 2; rs++) {
                    #pragma unroll
                    for (int cs = 0; cs < 2; cs++) {
                        int row = wm * 32 + f * 16 + qr + rs * 8;
                        int col = wn * 32 + jn * 8 + qc + cs;
                        float sq = qround8(sacc[f][jn][rs * 2 + cs]);
                        __half hh = __float2half_rn(sq);
                        __half ll = __float2half_rn(sq - __half2float(hh));
                        *(uint32_t*)(smem + AOS + (uint32_t)(row * 256 + ((col * 4) ^ ((row & 7) << 4)))) =
                            packu32(hh, ll);
                    }
                }
            }
        }
        __syncthreads();

        // ---- phase 2: z += s x v (K = 128 limb-halves, both vt buffers) ----
        #pragma unroll
        for (int kk = 0; kk < 8; kk++) {
            uint32_t a[2][4];
            #pragma unroll
            for (int f = 0; f < 2; f++)
                ldm_x4(a[f], sb + AOS + SWP(256, wm * 32 + f * 16 + arow_l, kk * 32 + achk));
            #pragma unroll
            for (int buf = 0; buf < 2; buf++) {
                uint32_t base = sV + buf * 16384;
                #pragma unroll
                for (int g = 0; g < 2; g++) {
                    uint32_t b4[4];
                    ldm_x4(b4, base + SWP(256, wn * 32 + g * 16 + brow_l, kk * 32 + bchk));
                    #pragma unroll
                    for (int f = 0; f < 2; f++) {
                        mma16816(zacc[f][g * 2 + 0], a[f], b4 + 0);
                        mma16816(zacc[f][g * 2 + 1], a[f], b4 + 2);
                    }
                }
            }
        }
    }

    // epilogue: quantize z (clamped), limb-split, write zc layout for proj GEMM
    const int b = bh / H_, h = bh - b * H_;
    #pragma unroll
    for (int f = 0; f < 2; f++) {
        #pragma unroll
        for (int jn = 0; jn < 4; jn++) {
            #pragma unroll
            for (int rs = 0; rs < 2; rs++) {
                #pragma unroll
                for (int cs = 0; cs < 2; cs++) {
                    int n = q0 + wm * 32 + f * 16 + qr + rs * 8;
                    int e = wn * 32 + jn * 8 + qc + cs;
                    float zq = q16_8c(zacc[f][jn][rs * 2 + cs]);
                    __half hh = __float2half_rn(zq);
                    __half ll = __float2half_rn(zq - __half2float(hh));
                    g_zl[((long)(b * N_ + n)) * KH2 + h * DH_ + e] = packu32(hh, ll);
                }
            }
        }
    }
}

// ---------------- launch ----------------
extern "C" void kernel_launch(void* const* d_in, const int* in_sizes, int n_in,
                              void* d_out, int out_size) {
    const float* q_in = (const float*)d_in[0];
    const float* wqkv = (const float*)d_in[1];
    const float* bqkv = (const float*)d_in[2];
    const float* wp   = (const float*)d_in[3];
    const float* bp   = (const float*)d_in[4];
    float* out = (float*)d_out;

    const long total = (long)M1 * DIM_ + (long)NC1 * DIM_ + (long)DIM_ * DIM_ + NC1 + DIM_;
    prep_kernel<<<(unsigned)((total + 255) / 256), 256>>>(q_in, wqkv, bqkv, wp, bp);

    const int gemm_smem = 3 * GSTG;   // 147456
    cudaFuncSetAttribute(gemm_qkv_tc, cudaFuncAttributeMaxDynamicSharedMemorySize, gemm_smem);
    gemm_qkv_tc<<<dim3(NC1 / 128, M1 / 128), 256, gemm_smem>>>();       // (18, 32)

    cudaFuncSetAttribute(attn_tc_kernel, cudaFuncAttributeMaxDynamicSharedMemorySize, ATTN_SMEM);
    attn_tc_kernel<<<dim3(N_ / 128, B_ * H_), 256, ATTN_SMEM>>>();      // (16, 24)

    cudaFuncSetAttribute(gemm_proj_tc, cudaFuncAttributeMaxDynamicSharedMemorySize, gemm_smem);
    gemm_proj_tc<<<dim3(DIM_ / 128, M1 / 128), 256, gemm_smem>>>(out);  // (6, 32)
}